// round 13
// baseline (speedup 1.0000x reference)
#include <cuda_runtime.h>
#include <cuda_bf16.h>
#include <math.h>

// HSIC_1855425872455: X [2048,16] fp32 -> scalar fp32
// R13 = R12 + (a) rotated-float4 smem layout for s_xj -> 4x LDS.128
// conflict-free per step (was 16x LDS.32), (b) #pragma unroll 4 sweep.
// All phase logic identical to the passing R12.

#define N 2048
#define F 16
#define NPAIR 120
#define TILE 64
#define NT (N / TILE)              // 32
#define NBLK (NT * (NT + 1) / 2)   // 528
#define GRID 264                   // x2 tiles each
#define TRI16(a,b) ((a)*15 - (a)*((a)-1)/2 + ((b)-(a)-1))

__device__ float    g_A[N * F];
__device__ float    g_ps[32 * F];
__device__ float    g_pq[32 * F];
__device__ double   g_T[NPAIR];
__device__ double   g_Dm[NPAIR];
__device__ double   g_S[F];
__device__ unsigned g_sync0, g_sync1, g_sync2;   // monotonic tickets

__device__ __forceinline__ float ex2f(float x) {
    float r; asm("ex2.approx.f32 %0, %1;" : "=f"(r) : "f"(x)); return r;
}
__device__ __forceinline__ float wred(float v) {
    v += __shfl_xor_sync(0xffffffffu, v, 16);
    v += __shfl_xor_sync(0xffffffffu, v, 8);
    v += __shfl_xor_sync(0xffffffffu, v, 4);
    v += __shfl_xor_sync(0xffffffffu, v, 2);
    v += __shfl_xor_sync(0xffffffffu, v, 1);
    return v;
}
__device__ __forceinline__ void tile_decode(int idx, int& ti, int& tj) {
    int a = 0, rem = idx;
    while (rem >= NT - a) { rem -= NT - a; a++; }
    ti = a; tj = a + rem;
}
__device__ __forceinline__ void gsync(unsigned* ctr) {
    __syncthreads();
    if (threadIdx.x == 0) {
        __threadfence();
        unsigned t = atomicAdd(ctr, 1u);
        unsigned target = (t / GRID + 1u) * GRID;
        while (*(volatile unsigned*)ctr < target) __nanosleep(64);
        __threadfence();
    }
    __syncthreads();
}

// Chain-free systolic sweep over one 32-row x 32-col band.
// s_xj rows are stored rotated: float4 group g of row r lives at 16B-slot
// ((g + r) & 7) of a 32-float row -> LDS.128 reads are conflict-free for the
// lane->row permutation jl = (l+s)&31.
template <bool DIAG>
__device__ __forceinline__ void tile_sweep(
    const float* __restrict__ s_xj, const float xi[F],
    float rowA[F], float colA[F], float t[NPAIR],
    int il, int w_j, int l)
{
    #pragma unroll 4
    for (int s = 0; s < 32; s++) {
        const int jl = (w_j << 5) + ((l + s) & 31);
        const float B = DIAG ? ((il < jl) ? 0.f : -1024.0f) : 0.f;
        const float4* xjv = (const float4*)(s_xj + jl * 32);
        float4 g0 = xjv[(0 + jl) & 7];
        float4 g1 = xjv[(1 + jl) & 7];
        float4 g2 = xjv[(2 + jl) & 7];
        float4 g3 = xjv[(3 + jl) & 7];
        float xj[F] = {g0.x,g0.y,g0.z,g0.w, g1.x,g1.y,g1.z,g1.w,
                       g2.x,g2.y,g2.z,g2.w, g3.x,g3.y,g3.z,g3.w};
        float k[F];
        #pragma unroll
        for (int c = 0; c < F; c++) {
            float d = xi[c] - xj[c];
            float kk = ex2f(fmaf(d, -d, B));
            k[c] = kk;
            rowA[c] += kk;
        }
        #pragma unroll
        for (int a = 0; a < F; a++)
            #pragma unroll
            for (int b = a + 1; b < F; b++)
                t[TRI16(a, b)] = fmaf(k[a], k[b], t[TRI16(a, b)]);
        const int src = (l - s) & 31;
        #pragma unroll
        for (int c = 0; c < F; c++)
            colA[c] += __shfl_sync(0xffffffffu, k[c], src);
    }
}

__global__ __launch_bounds__(128, 2) void hsic_all(
    const float* __restrict__ X, float* __restrict__ out)
{
    const int tid = threadIdx.x;
    const int w = tid >> 5, l = tid & 31;
    const int w_i = w >> 1, w_j = w & 1;
    const int b = blockIdx.x;

    __shared__ float s_sc[F];
    __shared__ float s_xj[TILE * 32];        // rotated float4 layout
    __shared__ float s_row[4][32][17];
    __shared__ float s_col[4][32][17];
    __shared__ float s_t[4][NPAIR];
    __shared__ float s_ps[128], s_pq[128];
    __shared__ float s_sv4[4][F];
    __shared__ double s_red[128];

    // ---------------- Phase 0: stats partials + zeroing --------------------
    if (b < 32) {
        const int col = tid & 15, part = tid >> 4;   // 8 partials per column
        float s = 0.f, q = 0.f;
        #pragma unroll
        for (int r = part; r < TILE; r += 8) {
            float v = X[(b * TILE + r) * F + col];
            s += v;
            q = fmaf(v, v, q);
        }
        s_ps[tid] = s; s_pq[tid] = q;
        __syncthreads();
        #pragma unroll
        for (int off = 4; off >= 1; off >>= 1) {
            if (part < off) {
                s_ps[tid] += s_ps[tid + off * 16];
                s_pq[tid] += s_pq[tid + off * 16];
            }
            __syncthreads();
        }
        if (tid < F) {
            g_ps[b * F + tid] = s_ps[tid];
            g_pq[b * F + tid] = s_pq[tid];
        }
        float4* A4 = (float4*)g_A;
        A4[b * 256 + tid]       = make_float4(0.f, 0.f, 0.f, 0.f);
        A4[b * 256 + 128 + tid] = make_float4(0.f, 0.f, 0.f, 0.f);
        if (b == 0) {
            if (tid < NPAIR) { g_T[tid] = 0.0; g_Dm[tid] = 0.0; }
            if (tid < F) g_S[tid] = 0.0;
        }
    }
    gsync(&g_sync0);

    // ---------------- Phase 1: main ----------------------------------------
    if (tid < F) {
        float s = 0.f, q = 0.f;
        #pragma unroll 4
        for (int bb = 0; bb < 32; bb++) { s += g_ps[bb * F + tid]; q += g_pq[bb * F + tid]; }
        float m1 = s * (1.f / N), m2 = q * (1.f / N);
        float meanD = 2.f * (m2 - m1 * m1);
        s_sc[tid] = sqrtf(1.4426950408889634f / (2.f * meanD));
    }
    __syncthreads();

    {
        float t[NPAIR];
        #pragma unroll
        for (int e = 0; e < NPAIR; e++) t[e] = 0.f;

        #pragma unroll 1
        for (int rep = 0; rep < 2; rep++) {
            int ti, tj;
            tile_decode(b + rep * GRID, ti, tj);
            const int I0 = ti * TILE, J0 = tj * TILE;
            const bool diag = (ti == tj);

            // stage J tile: 64 rows x 4 float4 groups, rotated placement
            for (int q = tid; q < TILE * 4; q += 128) {
                const int r = q >> 2, g = q & 3;
                float4 v = *(const float4*)(X + (J0 + r) * F + g * 4);
                v.x *= s_sc[g * 4];     v.y *= s_sc[g * 4 + 1];
                v.z *= s_sc[g * 4 + 2]; v.w *= s_sc[g * 4 + 3];
                *(float4*)(s_xj + r * 32 + ((g + r) & 7) * 4) = v;
            }
            const int il = (w_i << 5) + l;
            float xi[F];
            {
                const float4* p = (const float4*)(X + (I0 + il) * F);
                float4 a = p[0], bv = p[1], c = p[2], d = p[3];
                xi[0]=a.x; xi[1]=a.y; xi[2]=a.z; xi[3]=a.w;
                xi[4]=bv.x; xi[5]=bv.y; xi[6]=bv.z; xi[7]=bv.w;
                xi[8]=c.x; xi[9]=c.y; xi[10]=c.z; xi[11]=c.w;
                xi[12]=d.x; xi[13]=d.y; xi[14]=d.z; xi[15]=d.w;
                #pragma unroll
                for (int cc = 0; cc < F; cc++) xi[cc] *= s_sc[cc];
            }
            float rowA[F], colA[F];
            #pragma unroll
            for (int c = 0; c < F; c++) { rowA[c] = 0.f; colA[c] = 0.f; }
            __syncthreads();

            if (diag) tile_sweep<true >(s_xj, xi, rowA, colA, t, il, w_j, l);
            else      tile_sweep<false>(s_xj, xi, rowA, colA, t, il, w_j, l);
            // lane l holds colA for column jl = w_j*32 + l

            #pragma unroll
            for (int c = 0; c < F; c++) {
                s_row[w][l][c] = rowA[c];
                s_col[w][l][c] = colA[c];
            }
            __syncthreads();
            for (int idx = tid; idx < TILE * F; idx += 128) {
                const int ii = idx >> 4, c = idx & 15;
                const int ib = ii >> 5, ir = ii & 31;
                float rv = s_row[ib * 2][ir][c] + s_row[ib * 2 + 1][ir][c];
                atomicAdd(&g_A[(I0 + ii) * F + c], rv);
                float cv = s_col[ib][ir][c] + s_col[ib + 2][ir][c];
                atomicAdd(&g_A[(J0 + ii) * F + c], cv);
            }
            __syncthreads();
        }

        #pragma unroll
        for (int e = 0; e < NPAIR; e++) t[e] = wred(t[e]);
        if (l == 0) {
            #pragma unroll
            for (int e = 0; e < NPAIR; e++) s_t[w][e] = t[e];
        }
        __syncthreads();
        for (int e = tid; e < NPAIR; e += 128)
            atomicAdd(&g_T[e],
                      (double)(s_t[0][e] + s_t[1][e] + s_t[2][e] + s_t[3][e]));
    }
    gsync(&g_sync1);

    // ---------------- Phase 2: distributed Dm/S (CTAs 0-31) -----------------
    if (b < 32) {
        // warp w: rows [64b + 16w, +16); lanes 16..31 contribute zeros
        float acc[NPAIR], sv[F];
        #pragma unroll
        for (int e = 0; e < NPAIR; e++) acc[e] = 0.f;
        #pragma unroll
        for (int c = 0; c < F; c++) sv[c] = 0.f;
        if (l < 16) {
            const int r = b * TILE + w * 16 + l;
            const float4* p = (const float4*)(g_A + r * F);
            float4 a = p[0], bv = p[1], c = p[2], d = p[3];
            float rv[F] = {a.x,a.y,a.z,a.w, bv.x,bv.y,bv.z,bv.w,
                           c.x,c.y,c.z,c.w, d.x,d.y,d.z,d.w};
            #pragma unroll
            for (int aa = 0; aa < F; aa++) {
                sv[aa] = rv[aa];
                #pragma unroll
                for (int bb = aa + 1; bb < F; bb++)
                    acc[TRI16(aa, bb)] = rv[aa] * rv[bb];
            }
        }
        #pragma unroll
        for (int e = 0; e < NPAIR; e++) acc[e] = wred(acc[e]);
        #pragma unroll
        for (int c = 0; c < F; c++) sv[c] = wred(sv[c]);
        if (l == 0) {
            #pragma unroll
            for (int e = 0; e < NPAIR; e++) s_t[w][e] = acc[e];
            #pragma unroll
            for (int c = 0; c < F; c++) s_sv4[w][c] = sv[c];
        }
        __syncthreads();
        // strided scatter covers all NPAIR + F slots with 128 threads
        for (int e2 = tid; e2 < NPAIR + F; e2 += 128) {
            if (e2 < NPAIR) {
                atomicAdd(&g_Dm[e2],
                          (double)(s_t[0][e2] + s_t[1][e2] + s_t[2][e2] + s_t[3][e2]));
            } else {
                const int c = e2 - NPAIR;
                atomicAdd(&g_S[c],
                          (double)(s_sv4[0][c] + s_sv4[1][c] + s_sv4[2][c] + s_sv4[3][c]));
            }
        }
    }
    gsync(&g_sync2);

    // ---------------- Phase 3: combine (CTA 0) -------------------------------
    if (b != 0) return;
    {
        double v = 0.0;
        if (tid < NPAIR) {
            int a = 0, rem = tid;
            while (rem >= 15 - a) { rem -= 15 - a; a++; }
            int bb2 = a + 1 + rem;
            const double n = (double)N;
            double T = 2.0 * g_T[tid];              // strict-upper weight
            double c0 = 1.0 / (n * (n - 3.0));
            double h = c0 * (T + g_S[a] * g_S[bb2] / ((n - 1.0) * (n - 2.0))
                               - (2.0 / (n - 2.0)) * g_Dm[tid]);
            v = h * h;
        }
        s_red[tid] = v;
        __syncthreads();
        #pragma unroll
        for (int off = 64; off >= 1; off >>= 1) {
            if (tid < off) s_red[tid] += s_red[tid + off];
            __syncthreads();
        }
        if (tid == 0) out[0] = (float)s_red[0];
    }
}

extern "C" void kernel_launch(void* const* d_in, const int* in_sizes, int n_in,
                              void* d_out, int out_size) {
    const float* X = (const float*)d_in[0];
    hsic_all<<<GRID, 128>>>(X, (float*)d_out);
}